// round 4
// baseline (speedup 1.0000x reference)
#include <cuda_runtime.h>
#include <cstdint>

#define N_NODES 50000
#define E_EDGES 800000
#define IN_C 10
#define HID 96
#define OUT_C 48

// Scratch (device globals — no allocation allowed in kernel_launch)
__device__ float g_deg[N_NODES];
__device__ float g_dis[N_NODES];                 // rsqrt(deg)
__device__ float g_aggx[N_NODES * IN_C];         // aggregated input features
__device__ float g_h[N_NODES * HID];             // relu(aggx @ W1 + b1)
__device__ float g_aggh[N_NODES * HID];          // aggregated hidden features

// --- K0: zero degree array (graph replays require re-init every launch) ---
__global__ void k0_zero_deg() {
    int i = blockIdx.x * blockDim.x + threadIdx.x;
    if (i < N_NODES) g_deg[i] = 0.0f;
}

// --- K1: in-degree count over col (self-loop added later as +1) ---
// edge_index is int32 (JAX x64 disabled downcasts the "int64" randint).
__global__ void k1_degree(const int* __restrict__ ei) {
    int e = blockIdx.x * blockDim.x + threadIdx.x;
    if (e < E_EDGES) {
        int c = ei[E_EDGES + e];
        atomicAdd(&g_deg[c], 1.0f);
    }
}

// --- K2: dis = rsqrt(deg+1); init aggx with self-loop term x[i]/deg ---
__global__ void k2_dis_init_aggx(const float* __restrict__ x) {
    int i = blockIdx.x * blockDim.x + threadIdx.x;
    if (i < N_NODES) {
        float d = g_deg[i] + 1.0f;      // + self loop
        float inv = 1.0f / d;
        g_dis[i] = rsqrtf(d);
        #pragma unroll
        for (int f = 0; f < IN_C; f++)
            g_aggx[i * IN_C + f] = x[i * IN_C + f] * inv;
    }
}

// --- K3: edge aggregation of raw x (10 features, thread per edge) ---
__global__ void k3_aggx_edges(const int* __restrict__ ei,
                              const float* __restrict__ x) {
    int e = blockIdx.x * blockDim.x + threadIdx.x;
    if (e < E_EDGES) {
        int r = ei[e];
        int c = ei[E_EDGES + e];
        float nrm = g_dis[r] * g_dis[c];
        const float* xr = x + (size_t)r * IN_C;
        float* ac = g_aggx + (size_t)c * IN_C;
        #pragma unroll
        for (int f = 0; f < IN_C; f++)
            atomicAdd(&ac[f], nrm * xr[f]);
    }
}

// --- K4: h = relu(aggx @ W1 + b1); init aggh with self-loop term h/deg ---
__global__ void k4_hidden(const float* __restrict__ W1, const float* __restrict__ b1) {
    __shared__ float sW[IN_C * HID];   // 3.84 KB
    for (int t = threadIdx.x; t < IN_C * HID; t += blockDim.x) sW[t] = W1[t];
    __syncthreads();
    int idx = blockIdx.x * blockDim.x + threadIdx.x;   // n*HID + f
    if (idx < N_NODES * HID) {
        int n = idx / HID, f = idx % HID;
        float s = b1[f];
        const float* ax = g_aggx + (size_t)n * IN_C;
        #pragma unroll
        for (int i = 0; i < IN_C; i++)
            s = fmaf(ax[i], sW[i * HID + f], s);
        s = fmaxf(s, 0.0f);
        g_h[idx] = s;
        float dis = g_dis[n];
        g_aggh[idx] = s * dis * dis;   // self-loop: h[n] / deg[n]
    }
}

// --- K5: edge aggregation of h (96 features, one warp per edge) ---
// Coalesced 128B reads of h[row], REDG scatter-adds into aggh[col].
__global__ void k5_aggh_edges(const int* __restrict__ ei) {
    int gtid = blockIdx.x * blockDim.x + threadIdx.x;
    int e = gtid >> 5;
    int lane = gtid & 31;
    if (e >= E_EDGES) return;
    int r = ei[e];
    int c = ei[E_EDGES + e];
    float nrm = g_dis[r] * g_dis[c];
    const float* hr = g_h + (size_t)r * HID;
    float* ac = g_aggh + (size_t)c * HID;
    #pragma unroll
    for (int k = 0; k < HID / 32; k++) {
        float v = hr[k * 32 + lane];
        atomicAdd(&ac[k * 32 + lane], nrm * v);
    }
}

// --- K6: mu = aggh @ Wmu + bmu ; logstd = aggh @ Wls + bls (fused) ---
// blockDim = 96 (one output column per thread), grid-stride over nodes.
__global__ void k6_out(const float* __restrict__ Wmu, const float* __restrict__ bmu,
                       const float* __restrict__ Wls, const float* __restrict__ bls,
                       float* __restrict__ out) {
    __shared__ float sW[HID][HID];   // 36.9 KB: cols [0,48)=Wmu, [48,96)=Wls
    __shared__ float srow[HID];
    for (int t = threadIdx.x; t < HID * HID; t += blockDim.x) {
        int i = t / HID, j = t % HID;
        sW[i][j] = (j < OUT_C) ? Wmu[i * OUT_C + j]
                               : Wls[i * OUT_C + (j - OUT_C)];
    }
    __syncthreads();
    int j = threadIdx.x;   // 0..95
    float bias = (j < OUT_C) ? bmu[j] : bls[j - OUT_C];
    for (int n = blockIdx.x; n < N_NODES; n += gridDim.x) {
        srow[j] = g_aggh[(size_t)n * HID + j];
        __syncthreads();
        float s = bias;
        #pragma unroll
        for (int i = 0; i < HID; i++)
            s = fmaf(srow[i], sW[i][j], s);
        if (j < OUT_C)
            out[(size_t)n * OUT_C + j] = s;
        else
            out[(size_t)N_NODES * OUT_C + (size_t)n * OUT_C + (j - OUT_C)] = s;
        __syncthreads();
    }
}

extern "C" void kernel_launch(void* const* d_in, const int* in_sizes, int n_in,
                              void* d_out, int out_size) {
    const float* x   = (const float*)d_in[0];
    const int*   ei  = (const int*)d_in[1];
    const float* W1  = (const float*)d_in[2];
    const float* b1  = (const float*)d_in[3];
    const float* Wmu = (const float*)d_in[4];
    const float* bmu = (const float*)d_in[5];
    const float* Wls = (const float*)d_in[6];
    const float* bls = (const float*)d_in[7];
    float* out = (float*)d_out;

    k0_zero_deg<<<(N_NODES + 255) / 256, 256>>>();
    k1_degree<<<(E_EDGES + 255) / 256, 256>>>(ei);
    k2_dis_init_aggx<<<(N_NODES + 255) / 256, 256>>>(x);
    k3_aggx_edges<<<(E_EDGES + 255) / 256, 256>>>(ei, x);
    k4_hidden<<<(N_NODES * HID + 255) / 256, 256>>>(W1, b1);
    k5_aggh_edges<<<(E_EDGES * 32 + 255) / 256, 256>>>(ei);
    k6_out<<<2048, HID>>>(Wmu, bmu, Wls, bls, out);
}

// round 6
// speedup vs baseline: 1.1699x; 1.1699x over previous
#include <cuda_runtime.h>
#include <cstdint>

#define N_NODES 50000
#define E_EDGES 800000
#define IN_C 10
#define AGGX_STRIDE 12          // pad 10 -> 12 floats so every row is 16B aligned
#define HID 96
#define OUT_C 48

// Scratch (device globals — no allocation allowed in kernel_launch)
__device__ float g_deg[N_NODES];
__device__ float g_dis[N_NODES];                    // rsqrt(deg)
__device__ float g_aggx[N_NODES * AGGX_STRIDE];     // aggregated input features (padded)
__device__ float g_h[N_NODES * HID];                // relu(aggx @ W1 + b1)
__device__ float g_aggh[N_NODES * HID];             // aggregated hidden features

// ---- vectorized global reductions (PTX ISA 8.3+, sm_90+) ----
__device__ __forceinline__ void red_add_v4(float* addr, float a, float b, float c, float d) {
    asm volatile("red.global.add.v4.f32 [%0], {%1,%2,%3,%4};"
                 :: "l"(addr), "f"(a), "f"(b), "f"(c), "f"(d) : "memory");
}
__device__ __forceinline__ void red_add_v2(float* addr, float a, float b) {
    asm volatile("red.global.add.v2.f32 [%0], {%1,%2};"
                 :: "l"(addr), "f"(a), "f"(b) : "memory");
}

// --- K0: zero degree array (graph replays require re-init every launch) ---
__global__ void k0_zero_deg() {
    int i = blockIdx.x * blockDim.x + threadIdx.x;
    if (i < N_NODES) g_deg[i] = 0.0f;
}

// --- K1: in-degree count over col (self-loop added later as +1) ---
__global__ void k1_degree(const int* __restrict__ ei) {
    int e = blockIdx.x * blockDim.x + threadIdx.x;
    if (e < E_EDGES) {
        int c = ei[E_EDGES + e];
        atomicAdd(&g_deg[c], 1.0f);
    }
}

// --- K2: dis = rsqrt(deg+1); init aggx with self-loop term x[i]/deg ---
__global__ void k2_dis_init_aggx(const float* __restrict__ x) {
    int i = blockIdx.x * blockDim.x + threadIdx.x;
    if (i < N_NODES) {
        float d = g_deg[i] + 1.0f;      // + self loop
        float inv = 1.0f / d;
        g_dis[i] = rsqrtf(d);
        #pragma unroll
        for (int f = 0; f < IN_C; f++)
            g_aggx[i * AGGX_STRIDE + f] = x[i * IN_C + f] * inv;
    }
}

// --- K3: edge aggregation of raw x (10 feats; 3 vector REDGs per edge) ---
__global__ void k3_aggx_edges(const int* __restrict__ ei,
                              const float* __restrict__ x) {
    int e = blockIdx.x * blockDim.x + threadIdx.x;
    if (e < E_EDGES) {
        int r = ei[e];
        int c = ei[E_EDGES + e];
        float nrm = g_dis[r] * g_dis[c];
        const float* xr = x + (size_t)r * IN_C;
        float v[IN_C];
        #pragma unroll
        for (int f = 0; f < IN_C; f++) v[f] = nrm * xr[f];
        float* ac = g_aggx + (size_t)c * AGGX_STRIDE;   // 16B-aligned row
        red_add_v4(ac,     v[0], v[1], v[2], v[3]);
        red_add_v4(ac + 4, v[4], v[5], v[6], v[7]);
        red_add_v2(ac + 8, v[8], v[9]);
    }
}

// --- K4: h = relu(aggx @ W1 + b1); init aggh with self-loop term h/deg ---
__global__ void k4_hidden(const float* __restrict__ W1, const float* __restrict__ b1) {
    __shared__ float sW[IN_C * HID];   // 3.84 KB
    for (int t = threadIdx.x; t < IN_C * HID; t += blockDim.x) sW[t] = W1[t];
    __syncthreads();
    int idx = blockIdx.x * blockDim.x + threadIdx.x;   // n*HID + f
    if (idx < N_NODES * HID) {
        int n = idx / HID, f = idx % HID;
        float s = b1[f];
        const float* ax = g_aggx + (size_t)n * AGGX_STRIDE;
        #pragma unroll
        for (int i = 0; i < IN_C; i++)
            s = fmaf(ax[i], sW[i * HID + f], s);
        s = fmaxf(s, 0.0f);
        g_h[idx] = s;
        float dis = g_dis[n];
        g_aggh[idx] = s * dis * dis;   // self-loop: h[n] / deg[n]
    }
}

// --- K5: edge aggregation of h (96 feats; 24 v4-REDGs per edge) ---
// Dense mapping: thread i handles edge e = i/24, 16B chunk c4 = i%24.
// LDG.128 gather of h[row], red.global.add.v4 scatter into aggh[col].
__global__ void k5_aggh_edges(const int* __restrict__ ei) {
    long long i = (long long)blockIdx.x * blockDim.x + threadIdx.x;
    if (i >= (long long)E_EDGES * 24) return;
    int e  = (int)(i / 24);
    int c4 = (int)(i % 24);
    int r = ei[e];
    int c = ei[E_EDGES + e];
    float nrm = g_dis[r] * g_dis[c];
    const float4 hv = *(const float4*)(g_h + (size_t)r * HID + c4 * 4);
    float* ac = g_aggh + (size_t)c * HID + c4 * 4;
    red_add_v4(ac, nrm * hv.x, nrm * hv.y, nrm * hv.z, nrm * hv.w);
}

// --- K6: mu = aggh @ Wmu + bmu ; logstd = aggh @ Wls + bls (fused) ---
// blockDim = 96 (one output column per thread), grid-stride over nodes.
__global__ void k6_out(const float* __restrict__ Wmu, const float* __restrict__ bmu,
                       const float* __restrict__ Wls, const float* __restrict__ bls,
                       float* __restrict__ out) {
    __shared__ float sW[HID][HID];   // 36.9 KB: cols [0,48)=Wmu, [48,96)=Wls
    __shared__ float srow[HID];
    for (int t = threadIdx.x; t < HID * HID; t += blockDim.x) {
        int i = t / HID, j = t % HID;
        sW[i][j] = (j < OUT_C) ? Wmu[i * OUT_C + j]
                               : Wls[i * OUT_C + (j - OUT_C)];
    }
    __syncthreads();
    int j = threadIdx.x;   // 0..95
    float bias = (j < OUT_C) ? bmu[j] : bls[j - OUT_C];
    for (int n = blockIdx.x; n < N_NODES; n += gridDim.x) {
        srow[j] = g_aggh[(size_t)n * HID + j];
        __syncthreads();
        float s = bias;
        #pragma unroll
        for (int i = 0; i < HID; i++)
            s = fmaf(srow[i], sW[i][j], s);
        if (j < OUT_C)
            out[(size_t)n * OUT_C + j] = s;
        else
            out[(size_t)N_NODES * OUT_C + (size_t)n * OUT_C + (j - OUT_C)] = s;
        __syncthreads();
    }
}

extern "C" void kernel_launch(void* const* d_in, const int* in_sizes, int n_in,
                              void* d_out, int out_size) {
    const float* x   = (const float*)d_in[0];
    const int*   ei  = (const int*)d_in[1];
    const float* W1  = (const float*)d_in[2];
    const float* b1  = (const float*)d_in[3];
    const float* Wmu = (const float*)d_in[4];
    const float* bmu = (const float*)d_in[5];
    const float* Wls = (const float*)d_in[6];
    const float* bls = (const float*)d_in[7];
    float* out = (float*)d_out;

    k0_zero_deg<<<(N_NODES + 255) / 256, 256>>>();
    k1_degree<<<(E_EDGES + 255) / 256, 256>>>(ei);
    k2_dis_init_aggx<<<(N_NODES + 255) / 256, 256>>>(x);
    k3_aggx_edges<<<(E_EDGES + 255) / 256, 256>>>(ei, x);
    k4_hidden<<<(N_NODES * HID + 255) / 256, 256>>>(W1, b1);
    long long k5_threads = (long long)E_EDGES * 24;
    k5_aggh_edges<<<(unsigned)((k5_threads + 255) / 256), 256>>>(ei);
    k6_out<<<2048, HID>>>(Wmu, bmu, Wls, bls, out);
}

// round 8
// speedup vs baseline: 1.3309x; 1.1375x over previous
#include <cuda_runtime.h>
#include <cstdint>

#define N_NODES 50000
#define E_EDGES 800000
#define IN_C 10
#define AGGX_STRIDE 12
#define HID 96
#define OUT_C 48

#define SCAN_T 1024
#define SCAN_CHUNK 49   // ceil(50000/1024)

// Scratch (device globals — no allocation allowed in kernel_launch)
__device__ int   g_deg[N_NODES];
__device__ int   g_fill[N_NODES];
__device__ int   g_ptr[N_NODES + 1];
__device__ int   g_srow[E_EDGES];                   // row indices bucketed by col
__device__ float g_dis[N_NODES];                    // rsqrt(deg+1)
__device__ float g_aggx[N_NODES * AGGX_STRIDE];
__device__ float g_h[N_NODES * HID];
__device__ float g_aggh[N_NODES * HID];

// --- K0: zero degree + fill counters (re-init every graph replay) ---
__global__ void k0_zero() {
    int i = blockIdx.x * blockDim.x + threadIdx.x;
    if (i < N_NODES) { g_deg[i] = 0; g_fill[i] = 0; }
}

// --- K1: in-degree histogram over col ---
__global__ void k1_degree(const int* __restrict__ ei) {
    int e = blockIdx.x * blockDim.x + threadIdx.x;
    if (e < E_EDGES) atomicAdd(&g_deg[ei[E_EDGES + e]], 1);
}

// --- K2: exclusive prefix sum of deg -> g_ptr (single block, chunked) ---
__global__ void k2_scan() {
    __shared__ int wsum[32];
    int t = threadIdx.x;
    int base = t * SCAN_CHUNK;
    int s = 0;
    for (int k = 0; k < SCAN_CHUNK; k++) {
        int i = base + k;
        if (i < N_NODES) s += g_deg[i];
    }
    int lane = t & 31, w = t >> 5;
    int v = s;
    #pragma unroll
    for (int o = 1; o < 32; o <<= 1) {
        int u = __shfl_up_sync(~0u, v, o);
        if (lane >= o) v += u;
    }
    if (lane == 31) wsum[w] = v;
    __syncthreads();
    if (w == 0) {
        int z = wsum[lane];
        #pragma unroll
        for (int o = 1; o < 32; o <<= 1) {
            int u = __shfl_up_sync(~0u, z, o);
            if (lane >= o) z += u;
        }
        wsum[lane] = z;
    }
    __syncthreads();
    int excl = v - s + ((w > 0) ? wsum[w - 1] : 0);
    int run = excl;
    for (int k = 0; k < SCAN_CHUNK; k++) {
        int i = base + k;
        if (i < N_NODES) { g_ptr[i] = run; run += g_deg[i]; }
    }
    if (t == SCAN_T - 1) g_ptr[N_NODES] = run;
}

// --- K3: dis = rsqrt(deg+1) ---
__global__ void k3_dis() {
    int i = blockIdx.x * blockDim.x + threadIdx.x;
    if (i < N_NODES) g_dis[i] = rsqrtf((float)g_deg[i] + 1.0f);
}

// --- K4: bucket-fill rows by destination col ---
__global__ void k4_fill(const int* __restrict__ ei) {
    int e = blockIdx.x * blockDim.x + threadIdx.x;
    if (e < E_EDGES) {
        int r = ei[e];
        int c = ei[E_EDGES + e];
        int p = atomicAdd(&g_fill[c], 1);
        g_srow[g_ptr[c] + p] = r;
    }
}

// --- K5: pull-mode aggregation of raw x (16 threads per node, f<10 active) ---
__global__ void k5_aggx(const float* __restrict__ x) {
    int tid = blockIdx.x * blockDim.x + threadIdx.x;
    int n = tid >> 4;
    int f = tid & 15;
    if (n >= N_NODES || f >= IN_C) return;
    float dn = g_dis[n];
    int start = g_ptr[n], end = g_ptr[n + 1];
    float acc = 0.0f;
    for (int j = start; j < end; j++) {
        int r = g_srow[j];
        acc = fmaf(g_dis[r], x[(size_t)r * IN_C + f], acc);
    }
    // total = dn * sum(dis_r * x_r) + x_n * dn^2   (self-loop)
    g_aggx[(size_t)n * AGGX_STRIDE + f] =
        fmaf(acc, dn, x[(size_t)n * IN_C + f] * dn * dn);
}

// --- K6: h = relu(aggx @ W1 + b1) ---
__global__ void k6_hidden(const float* __restrict__ W1, const float* __restrict__ b1) {
    __shared__ float sW[IN_C * HID];
    for (int t = threadIdx.x; t < IN_C * HID; t += blockDim.x) sW[t] = W1[t];
    __syncthreads();
    int idx = blockIdx.x * blockDim.x + threadIdx.x;
    if (idx < N_NODES * HID) {
        int n = idx / HID, f = idx % HID;
        float s = b1[f];
        const float* ax = g_aggx + (size_t)n * AGGX_STRIDE;
        #pragma unroll
        for (int i = 0; i < IN_C; i++)
            s = fmaf(ax[i], sW[i * HID + f], s);
        g_h[idx] = fmaxf(s, 0.0f);
    }
}

// --- K7: pull-mode aggregation of h (warp per node, 3 feats per lane) ---
__global__ void k7_aggh() {
    int wid = (blockIdx.x * blockDim.x + threadIdx.x) >> 5;
    int lane = threadIdx.x & 31;
    if (wid >= N_NODES) return;
    int n = wid;
    float dn = g_dis[n];
    int start = g_ptr[n], end = g_ptr[n + 1];
    const float* hn = g_h + (size_t)n * HID;
    // self-loop term: h[n] * dn^2
    float a0 = hn[lane]      * dn * dn;
    float a1 = hn[32 + lane] * dn * dn;
    float a2 = hn[64 + lane] * dn * dn;
    for (int base = start; base < end; base += 32) {
        int m = min(32, end - base);
        int rr = 0; float dr = 0.0f;
        if (base + lane < end) {
            rr = g_srow[base + lane];
            dr = g_dis[rr];
        }
        for (int j = 0; j < m; j++) {
            int r = __shfl_sync(~0u, rr, j);
            float nrm = __shfl_sync(~0u, dr, j) * dn;
            const float* hr = g_h + (size_t)r * HID;
            a0 = fmaf(nrm, hr[lane],      a0);
            a1 = fmaf(nrm, hr[32 + lane], a1);
            a2 = fmaf(nrm, hr[64 + lane], a2);
        }
    }
    float* an = g_aggh + (size_t)n * HID;
    an[lane]      = a0;
    an[32 + lane] = a1;
    an[64 + lane] = a2;
}

// --- K8: mu/logstd = aggh @ {Wmu|Wls} + bias, 4 nodes per iteration ---
__global__ void k8_out(const float* __restrict__ Wmu, const float* __restrict__ bmu,
                       const float* __restrict__ Wls, const float* __restrict__ bls,
                       float* __restrict__ out) {
    __shared__ float sW[HID][HID];   // cols [0,48)=Wmu, [48,96)=Wls
    __shared__ float srow[4][HID];
    for (int t = threadIdx.x; t < HID * HID; t += blockDim.x) {
        int i = t / HID, j = t % HID;
        sW[i][j] = (j < OUT_C) ? Wmu[i * OUT_C + j]
                               : Wls[i * OUT_C + (j - OUT_C)];
    }
    __syncthreads();
    int j = threadIdx.x;   // 0..95
    float bias = (j < OUT_C) ? bmu[j] : bls[j - OUT_C];
    for (int n0 = blockIdx.x * 4; n0 < N_NODES; n0 += gridDim.x * 4) {
        #pragma unroll
        for (int k = 0; k < 4; k++)
            srow[k][j] = g_aggh[(size_t)(n0 + k) * HID + j];
        __syncthreads();
        float s0 = bias, s1 = bias, s2 = bias, s3 = bias;
        #pragma unroll
        for (int i = 0; i < HID; i++) {
            float w = sW[i][j];
            s0 = fmaf(srow[0][i], w, s0);
            s1 = fmaf(srow[1][i], w, s1);
            s2 = fmaf(srow[2][i], w, s2);
            s3 = fmaf(srow[3][i], w, s3);
        }
        size_t half = (size_t)N_NODES * OUT_C;
        if (j < OUT_C) {
            out[(size_t)(n0 + 0) * OUT_C + j] = s0;
            out[(size_t)(n0 + 1) * OUT_C + j] = s1;
            out[(size_t)(n0 + 2) * OUT_C + j] = s2;
            out[(size_t)(n0 + 3) * OUT_C + j] = s3;
        } else {
            int jj = j - OUT_C;
            out[half + (size_t)(n0 + 0) * OUT_C + jj] = s0;
            out[half + (size_t)(n0 + 1) * OUT_C + jj] = s1;
            out[half + (size_t)(n0 + 2) * OUT_C + jj] = s2;
            out[half + (size_t)(n0 + 3) * OUT_C + jj] = s3;
        }
        __syncthreads();
    }
}

extern "C" void kernel_launch(void* const* d_in, const int* in_sizes, int n_in,
                              void* d_out, int out_size) {
    const float* x   = (const float*)d_in[0];
    const int*   ei  = (const int*)d_in[1];
    const float* W1  = (const float*)d_in[2];
    const float* b1  = (const float*)d_in[3];
    const float* Wmu = (const float*)d_in[4];
    const float* bmu = (const float*)d_in[5];
    const float* Wls = (const float*)d_in[6];
    const float* bls = (const float*)d_in[7];
    float* out = (float*)d_out;

    k0_zero<<<(N_NODES + 255) / 256, 256>>>();
    k1_degree<<<(E_EDGES + 255) / 256, 256>>>(ei);
    k2_scan<<<1, SCAN_T>>>();
    k3_dis<<<(N_NODES + 255) / 256, 256>>>();
    k4_fill<<<(E_EDGES + 255) / 256, 256>>>(ei);
    k5_aggx<<<(N_NODES * 16 + 255) / 256, 256>>>(x);
    k6_hidden<<<(N_NODES * HID + 255) / 256, 256>>>(W1, b1);
    k7_aggh<<<(N_NODES * 32 + 255) / 256, 256>>>();
    k8_out<<<2048, HID>>>(Wmu, bmu, Wls, bls, out);
}